// round 12
// baseline (speedup 1.0000x reference)
#include <cuda_runtime.h>
#include <cuda_fp16.h>
#include <math.h>
#include <stdint.h>

#define B_   4
#define C_   512
#define T_   32
#define HW_  1024
#define NCOL (T_*HW_)            // 32768 columns per batch
#define TOT  (B_*C_*T_*HW_)

// Scratch
__device__ __half d_x16[TOT];      // fp16 x, [b][n][c] (n = t*1024+hw)
__device__ __half d_W16[1024*512]; // W2G = W2·diag(gamma), [m][k], fp16
__device__ __half d_u16[TOT];      // u  (fp16, [b][c][n])
__device__ __half d_vp16[TOT];     // v' (fp16, [b][c][n])
__device__ float  d_w2g1[1024];
__device__ float  d_w2b[1024];
__device__ float  d_psum[16384];
__device__ float  d_psum2[16384];
__device__ float  d_mean[B_*T_];
__device__ float  d_rstd[B_*T_];

__device__ __forceinline__ void cp16g(void* dst, const void* src) {
    unsigned d = (unsigned)__cvta_generic_to_shared(dst);
    asm volatile("cp.async.cg.shared.global [%0], [%1], 16;\n" :: "r"(d), "l"(src));
}

#define MMA_F16(d0,d1,d2,d3,a0,a1,a2,a3,b0,b1) \
    asm volatile("mma.sync.aligned.m16n8k16.row.col.f32.f16.f16.f32 " \
                 "{%0,%1,%2,%3},{%4,%5,%6,%7},{%8,%9},{%0,%1,%2,%3};" \
                 : "+f"(d0), "+f"(d1), "+f"(d2), "+f"(d3) \
                 : "r"(a0), "r"(a1), "r"(a2), "r"(a3), "r"(b0), "r"(b1))

#define MMA_TF32(d0,d1,d2,d3,a0,a1,a2,a3,b0,b1) \
    asm volatile("mma.sync.aligned.m16n8k8.row.col.f32.tf32.tf32.f32 " \
                 "{%0,%1,%2,%3},{%4,%5,%6,%7},{%8,%9},{%0,%1,%2,%3};" \
                 : "+f"(d0), "+f"(d1), "+f"(d2), "+f"(d3) \
                 : "r"(a0), "r"(a1), "r"(a2), "r"(a3), "r"(b0), "r"(b1))

__device__ __forceinline__ float tf32r(float x) {
    uint32_t r;
    asm("cvt.rna.tf32.f32 %0, %1;" : "=r"(r) : "f"(x));
    return __uint_as_float(r);
}

// ---------------------------------------------------------------------------
// prep_w2 (R10)
// ---------------------------------------------------------------------------
__global__ void prep_w2(const float* __restrict__ wq, const float* __restrict__ wk,
                        const float* __restrict__ wv, const float* __restrict__ wproj,
                        const float* __restrict__ gamma, const float* __restrict__ beta)
{
    int m = blockIdx.x;
    int tid = threadIdx.x;
    float lg = 0.f, lb = 0.f;
    #pragma unroll
    for (int jj = 0; jj < 2; jj++) {
        int j = jj * 256 + tid;
        float acc = 0.f;
        if (m < 512) {
            #pragma unroll 4
            for (int o = 0; o < 512; o++)
                acc += wq[o*512 + m] * wk[o*512 + j];
        } else {
            int i = m - 512;
            #pragma unroll 4
            for (int c = 0; c < 512; c++)
                acc += wproj[i*512 + c] * wv[c*512 + j];
        }
        __half wh = __float2half(acc * gamma[j]);
        d_W16[(size_t)m * 512 + j] = wh;
        lg += __half2float(wh);
        lb += acc * beta[j];
    }
    __shared__ float red[16];
    #pragma unroll
    for (int o = 16; o > 0; o >>= 1) {
        lg += __shfl_down_sync(0xffffffffu, lg, o);
        lb += __shfl_down_sync(0xffffffffu, lb, o);
    }
    int w = tid >> 5;
    if ((tid & 31) == 0) { red[w] = lg; red[8 + w] = lb; }
    __syncthreads();
    if (tid == 0) {
        float G = 0.f, Bv = 0.f;
        for (int k = 0; k < 8; k++) { G += red[k]; Bv += red[8 + k]; }
        d_w2g1[m] = G;
        d_w2b[m]  = Bv;
    }
}

// ---------------------------------------------------------------------------
// conv_x16 + LN partial sums (R10)
// ---------------------------------------------------------------------------
__global__ void conv_x16(const float* __restrict__ x)
{
    __shared__ float sT[64][65];
    __shared__ float rsum[8], rsum2[8];
    int b   = blockIdx.z;
    int c0  = blockIdx.y * 64;
    int n0t = blockIdx.x * 64;
    int tid = threadIdx.x;
    const float* xb = x + (size_t)b * C_ * NCOL;
    float s = 0.f, ss = 0.f;
    #pragma unroll
    for (int r = 0; r < 4; r++) {
        int flat = r * 256 + tid;
        int cr = flat >> 4, nq = flat & 15;
        float4 v = *reinterpret_cast<const float4*>(
            xb + (size_t)(c0 + cr) * NCOL + n0t + nq * 4);
        sT[cr][nq*4+0] = v.x; sT[cr][nq*4+1] = v.y;
        sT[cr][nq*4+2] = v.z; sT[cr][nq*4+3] = v.w;
        s  += v.x + v.y + v.z + v.w;
        ss += v.x*v.x + v.y*v.y + v.z*v.z + v.w*v.w;
    }
    #pragma unroll
    for (int o = 16; o > 0; o >>= 1) {
        s  += __shfl_down_sync(0xffffffffu, s,  o);
        ss += __shfl_down_sync(0xffffffffu, ss, o);
    }
    if ((tid & 31) == 0) { rsum[tid >> 5] = s; rsum2[tid >> 5] = ss; }
    __syncthreads();
    if (tid == 0) {
        float S = 0.f, SS = 0.f;
        #pragma unroll
        for (int k = 0; k < 8; k++) { S += rsum[k]; SS += rsum2[k]; }
        int t = blockIdx.x >> 4, nIn = blockIdx.x & 15;
        int pid = ((b * 32 + t) * 8 + blockIdx.y) * 16 + nIn;
        d_psum[pid]  = S;
        d_psum2[pid] = SS;
    }
    int nr = tid >> 2, cq = tid & 3;
    uint32_t pk[8];
    #pragma unroll
    for (int j = 0; j < 8; j++) {
        __half2 h2 = __floats2half2_rn(sT[cq*16 + j*2][nr], sT[cq*16 + j*2 + 1][nr]);
        pk[j] = *reinterpret_cast<uint32_t*>(&h2);
    }
    __half* dst = d_x16 + ((size_t)b * NCOL + n0t + nr) * 512 + c0 + cq * 16;
    *reinterpret_cast<uint4*>(dst)     = make_uint4(pk[0], pk[1], pk[2], pk[3]);
    *reinterpret_cast<uint4*>(dst + 8) = make_uint4(pk[4], pk[5], pk[6], pk[7]);
}

__global__ void reduce_stats()
{
    int g = blockIdx.x;
    int tid = threadIdx.x;
    float s  = d_psum[g * 128 + tid];
    float ss = d_psum2[g * 128 + tid];
    #pragma unroll
    for (int o = 16; o > 0; o >>= 1) {
        s  += __shfl_down_sync(0xffffffffu, s,  o);
        ss += __shfl_down_sync(0xffffffffu, ss, o);
    }
    __shared__ float sm[8];
    if ((tid & 31) == 0) { sm[tid >> 5] = s; sm[4 + (tid >> 5)] = ss; }
    __syncthreads();
    if (tid == 0) {
        float S = sm[0] + sm[1] + sm[2] + sm[3];
        float SS = sm[4] + sm[5] + sm[6] + sm[7];
        float invn = 1.f / (float)(C_ * HW_);
        float m = S * invn;
        float var = SS * invn - m * m;
        d_mean[g] = m;
        d_rstd[g] = rsqrtf(var + 1e-6f);
    }
}

// ---------------------------------------------------------------------------
// fp16 GEMM (R10): y = W16·x16^T per batch; u16/vp16 = fp16(rstd·y+bias), [c][n]
// ---------------------------------------------------------------------------
#define AROW 40
#define STH  (128*AROW)
#define STAGEH (2*STH)
#define GEMM_SMEM (4*STAGEH*2)   // 81920 B

__global__ __launch_bounds__(128, 2) void gemm_uv_f16()
{
    extern __shared__ __half smh[];
    int b  = blockIdx.z;
    int m0 = blockIdx.x * 128;
    int n0 = blockIdx.y * 128;
    const __half* xb = d_x16 + (size_t)b * NCOL * 512;
    int tid  = threadIdx.x;
    int lane = tid & 31;
    int w    = tid >> 5;
    int warpM = w >> 1, warpN = w & 1;
    int g = lane >> 2, tq = lane & 3;
    int am = warpM * 64 + g;
    int bn = warpN * 64 + g;

    float acc[4][8][4];
    #pragma unroll
    for (int i = 0; i < 4; i++)
        #pragma unroll
        for (int j = 0; j < 8; j++)
            #pragma unroll
            for (int r = 0; r < 4; r++) acc[i][j][r] = 0.f;

    auto load_stage = [&](int k0, int buf) {
        __half* As = smh + buf * STAGEH;
        __half* Bs = As + STH;
        #pragma unroll
        for (int r = 0; r < 4; r++) {
            int ch = r * 128 + tid;
            int row = ch >> 2;
            int q   = ch & 3;
            cp16g(As + row * AROW + q * 8, &d_W16[(size_t)(m0 + row) * 512 + k0 + q * 8]);
            cp16g(Bs + row * AROW + q * 8, &xb[(size_t)(n0 + row) * 512 + k0 + q * 8]);
        }
    };

    #pragma unroll
    for (int p = 0; p < 3; p++) {
        load_stage(p * 32, p);
        asm volatile("cp.async.commit_group;\n");
    }

    for (int it = 0; it < 16; it++) {
        asm volatile("cp.async.wait_group 2;\n");
        __syncthreads();

        const uint32_t* Asw = reinterpret_cast<const uint32_t*>(smh + (it & 3) * STAGEH);
        const uint32_t* Bsw = Asw + STH / 2;

        #pragma unroll
        for (int ks = 0; ks < 16; ks += 8) {
            uint32_t a[4][4], bq[8][2];
            #pragma unroll
            for (int mf = 0; mf < 4; mf++) {
                int r0 = (am + mf * 16) * 20 + ks + tq;
                int r1 = (am + mf * 16 + 8) * 20 + ks + tq;
                a[mf][0] = Asw[r0];
                a[mf][1] = Asw[r1];
                a[mf][2] = Asw[r0 + 4];
                a[mf][3] = Asw[r1 + 4];
            }
            #pragma unroll
            for (int nf = 0; nf < 8; nf++) {
                int rb = (bn + nf * 8) * 20 + ks + tq;
                bq[nf][0] = Bsw[rb];
                bq[nf][1] = Bsw[rb + 4];
            }
            #pragma unroll
            for (int mf = 0; mf < 4; mf++)
                #pragma unroll
                for (int nf = 0; nf < 8; nf++)
                    MMA_F16(acc[mf][nf][0], acc[mf][nf][1], acc[mf][nf][2], acc[mf][nf][3],
                            a[mf][0], a[mf][1], a[mf][2], a[mf][3],
                            bq[nf][0], bq[nf][1]);
        }
        if (it + 3 < 16)
            load_stage((it + 3) * 32, (it + 3) & 3);
        asm volatile("cp.async.commit_group;\n");
    }

    int tcol = blockIdx.y >> 3;
    int gidx = b * 32 + tcol;
    float rstdv = d_rstd[gidx];
    float rm    = rstdv * d_mean[gidx];
    bool isU = (m0 < 512);
    __half* outb = isU ? (d_u16  + (size_t)(b * 512 + m0)       * NCOL)
                       : (d_vp16 + (size_t)(b * 512 + m0 - 512) * NCOL);
    #pragma unroll
    for (int mf = 0; mf < 4; mf++) {
        int mrow = warpM * 64 + mf * 16 + g;
        int mg0 = m0 + mrow, mg1 = m0 + mrow + 8;
        float bias0 = d_w2b[mg0] - rm * d_w2g1[mg0];
        float bias1 = d_w2b[mg1] - rm * d_w2g1[mg1];
        #pragma unroll
        for (int nf = 0; nf < 8; nf++) {
            int ncol = n0 + warpN * 64 + nf * 8 + tq * 2;
            __half2 lo = __floats2half2_rn(rstdv * acc[mf][nf][0] + bias0,
                                           rstdv * acc[mf][nf][1] + bias0);
            __half2 hi = __floats2half2_rn(rstdv * acc[mf][nf][2] + bias1,
                                           rstdv * acc[mf][nf][3] + bias1);
            *reinterpret_cast<__half2*>(outb + (size_t)mrow * NCOL + ncol)       = lo;
            *reinterpret_cast<__half2*>(outb + (size_t)(mrow + 8) * NCOL + ncol) = hi;
        }
    }
}

// ---------------------------------------------------------------------------
// attn (R10 numerics, double-buffered smem):
//  HU[2] floats [0,18944): Hs(buf)=base+buf*9472, Us=Hs+4736 (stride 296)
//  Gs [0,9344)  (phase >=2, aliases HU buf0)      stride 292
//  VPs[2] at 9472 + buf*5376  (phase 4)           stride 168
//  Os at 20224 (5248)                             stride 164
//  gus 25472, bus 25728, smG[2][16] 25984, smB[2][16] 26016
// ---------------------------------------------------------------------------
#define HS_CSTR 296
#define GS_TSTR 292
#define VP_SSTR 168
#define OS_TSTR 164
#define ATTN_SMEM_FLOATS 26048

__global__ __launch_bounds__(256, 2) void attn_mma(const float* __restrict__ x,
                                                   const float* __restrict__ gamma,
                                                   const float* __restrict__ beta,
                                                   float* __restrict__ out)
{
    extern __shared__ float sm[];
    float* Gs  = sm;                 // phase >=2
    float* Os  = sm + 20224;
    float* gus = sm + 25472;
    float* bus = sm + 25728;
    float* smG = sm + 25984;         // [2][16]
    float* smB = sm + 26016;         // [2][16]

    int blk = blockIdx.x;
    int b   = blk >> 7;
    int hw0 = (blk & 127) * 8;
    int tid  = threadIdx.x;
    int lane = tid & 31;
    int px   = tid >> 5;
    int g = lane >> 2, tq = lane & 3;
    const size_t pixbase = (size_t)b * C_ * T_ * HW_ + hw0;
    const float*  xg = x      + pixbase;                 // fp32 (residual only)
    const __half* xh = d_x16  + (size_t)b * NCOL * 512;  // fp16 [n][c]
    const __half* ug = d_u16  + pixbase;
    const __half* vg = d_vp16 + pixbase;

    int s_ = tid >> 3, px_ = tid & 7;
    float gu = 0.f, bu = 0.f;

    float acc1[2][4][4];
    #pragma unroll
    for (int i = 0; i < 2; i++)
        #pragma unroll
        for (int j = 0; j < 4; j++)
            #pragma unroll
            for (int r = 0; r < 4; r++) acc1[i][j][r] = 0.f;

    uint4 pxh[2], pu4[2];
    auto prefetch1 = [&](int c0) {
        #pragma unroll
        for (int r = 0; r < 2; r++) {
            int flat = r * 256 + tid;            // q2 x px8 x t32
            int q   = flat & 1;
            int pxl = (flat >> 1) & 7;
            int t   = flat >> 4;
            pxh[r] = *reinterpret_cast<const uint4*>(
                xh + ((size_t)t * 1024 + hw0 + pxl) * 512 + c0 + q * 8);
        }
        #pragma unroll
        for (int r = 0; r < 2; r++) {
            int flat = r * 256 + tid;            // c16 x t32, half8 along hw
            int c = flat >> 5, t = flat & 31;
            pu4[r] = *reinterpret_cast<const uint4*>(
                ug + ((size_t)(c0 + c) * 32 + t) * 1024);
        }
    };
    auto store1 = [&](int c0, int buf) {
        float* Hs = sm + buf * 9472;
        float* Us = Hs + 4736;
        #pragma unroll
        for (int r = 0; r < 2; r++) {
            int flat = r * 256 + tid;
            int q   = flat & 1;
            int pxl = (flat >> 1) & 7;
            int t   = flat >> 4;
            const __half2* hp = reinterpret_cast<const __half2*>(&pxh[r]);
            #pragma unroll
            for (int j = 0; j < 4; j++) {
                float2 f = __half22float2(hp[j]);
                int c = q * 8 + j * 2;
                Hs[(c)     * HS_CSTR + t * 9 + pxl] = gamma[c0 + c]     * f.x;
                Hs[(c + 1) * HS_CSTR + t * 9 + pxl] = gamma[c0 + c + 1] * f.y;
            }
        }
        #pragma unroll
        for (int r = 0; r < 2; r++) {
            int flat = r * 256 + tid;
            int c = flat >> 5, t = flat & 31;
            int so = c * HS_CSTR + t * 9;
            const __half2* hp = reinterpret_cast<const __half2*>(&pu4[r]);
            #pragma unroll
            for (int j = 0; j < 4; j++) {
                float2 f = __half22float2(hp[j]);
                Us[so + j*2]     = f.x;
                Us[so + j*2 + 1] = f.y;
            }
        }
    };

    // -------- phase 1 (single sync per chunk) --------
    prefetch1(0);
    store1(0, 0);
    if (tid < 16)       smG[tid]      = gamma[tid];
    else if (tid < 32)  smB[tid - 16] = beta[tid - 16];
    prefetch1(16);
    __syncthreads();

    for (int i = 0; i < 32; i++) {
        int buf = i & 1;
        int c0  = i * 16;
        if (i + 1 < 32) {
            store1(c0 + 16, buf ^ 1);
            if (tid < 16)       smG[(buf^1)*16 + tid]      = gamma[c0 + 16 + tid];
            else if (tid < 32)  smB[(buf^1)*16 + tid - 16] = beta[c0 + 16 + tid - 16];
            if (i + 2 < 32) prefetch1(c0 + 32);
        }

        const uint32_t* Hu = reinterpret_cast<const uint32_t*>(sm + buf * 9472);
        const uint32_t* Uu = Hu + 4736;
        #pragma unroll
        for (int kk = 0; kk < 16; kk += 8) {
            uint32_t a[2][4], bq[4][2];
            #pragma unroll
            for (int mf = 0; mf < 2; mf++) {
                int base = (kk + tq) * HS_CSTR + (mf * 16 + g) * 9 + px;
                a[mf][0] = Hu[base];
                a[mf][1] = Hu[base + 72];
                a[mf][2] = Hu[base + 4 * HS_CSTR];
                a[mf][3] = Hu[base + 4 * HS_CSTR + 72];
            }
            #pragma unroll
            for (int nf = 0; nf < 4; nf++) {
                int base = (kk + tq) * HS_CSTR + (nf * 8 + g) * 9 + px;
                bq[nf][0] = Uu[base];
                bq[nf][1] = Uu[base + 4 * HS_CSTR];
            }
            #pragma unroll
            for (int mf = 0; mf < 2; mf++)
                #pragma unroll
                for (int nf = 0; nf < 4; nf++)
                    MMA_TF32(acc1[mf][nf][0], acc1[mf][nf][1], acc1[mf][nf][2], acc1[mf][nf][3],
                             a[mf][0], a[mf][1], a[mf][2], a[mf][3],
                             bq[nf][0], bq[nf][1]);
        }
        {
            const float* Usc = sm + buf * 9472 + 4736;
            #pragma unroll
            for (int c = 0; c < 16; c++) {
                float uv = Usc[c * HS_CSTR + s_ * 9 + px_];
                gu += smG[buf*16 + c] * uv;
                bu += smB[buf*16 + c] * uv;
            }
        }
        __syncthreads();
    }

    gus[s_ * 8 + px_] = gu;
    bus[s_ * 8 + px_] = bu;
    __syncthreads();

    // -------- corrected scaled logits -> Gs --------
    const float scale = 0.044194173824159216f;
    #pragma unroll
    for (int mf = 0; mf < 2; mf++) {
        int t0 = mf * 16 + g, t1 = t0 + 8;
        float r0 = d_rstd[b*32 + t0], m0v = d_mean[b*32 + t0];
        float r1 = d_rstd[b*32 + t1], m1v = d_mean[b*32 + t1];
        #pragma unroll
        for (int nf = 0; nf < 4; nf++) {
            int s0 = nf * 8 + tq * 2, s1 = s0 + 1;
            float gu0 = gus[s0*8 + px], bu0 = bus[s0*8 + px];
            float gu1 = gus[s1*8 + px], bu1 = bus[s1*8 + px];
            Gs[t0 * GS_TSTR + s0 * 9 + px] = (r0*(acc1[mf][nf][0] - m0v*gu0) + bu0) * scale;
            Gs[t0 * GS_TSTR + s1 * 9 + px] = (r0*(acc1[mf][nf][1] - m0v*gu1) + bu1) * scale;
            Gs[t1 * GS_TSTR + s0 * 9 + px] = (r1*(acc1[mf][nf][2] - m1v*gu0) + bu0) * scale;
            Gs[t1 * GS_TSTR + s1 * 9 + px] = (r1*(acc1[mf][nf][3] - m1v*gu1) + bu1) * scale;
        }
    }
    __syncthreads();

    // -------- causal softmax --------
    {
        int pxs = tid & 7;
        int t   = tid >> 3;
        int gb  = t * GS_TSTR + pxs;
        float mx = -1e30f;
        for (int s = 0; s <= t; s++) mx = fmaxf(mx, Gs[gb + s * 9]);
        float Z = 0.f;
        for (int s = 0; s <= t; s++) Z += __expf(Gs[gb + s * 9] - mx);
        float iz = 1.f / Z;
        for (int s = 0; s < 32; s++) {
            float v = (s <= t) ? __expf(Gs[gb + s * 9] - mx) * iz : 0.f;
            Gs[gb + s * 9] = tf32r(v);
        }
    }
    // (loop-top sync of phase 4 orders these writes before MMA reads)

    // -------- phase 4: out = G @ vp^T + x (double-buffered VPs) --------
    const uint32_t* Gu = reinterpret_cast<const uint32_t*>(Gs);
    uint4 pv4[2];
    auto prefetch_v = [&](int oc) {
        #pragma unroll
        for (int r = 0; r < 2; r++) {
            int flat = r * 256 + tid;
            int s = flat >> 4, o = flat & 15;
            pv4[r] = *reinterpret_cast<const uint4*>(
                vg + ((size_t)(oc + o) * 32 + s) * 1024);
        }
    };
    auto store_v = [&](int buf) {
        float* VPs = sm + 9472 + buf * 5376;
        #pragma unroll
        for (int r = 0; r < 2; r++) {
            int flat = r * 256 + tid;
            int s = flat >> 4, o = flat & 15;
            int so = s * VP_SSTR + o * 9;
            const __half2* hp = reinterpret_cast<const __half2*>(&pv4[r]);
            #pragma unroll
            for (int j = 0; j < 4; j++) {
                float2 f = __half22float2(hp[j]);
                VPs[so + j*2]     = f.x;
                VPs[so + j*2 + 1] = f.y;
            }
        }
    };

    prefetch_v(0);
    store_v(0);
    prefetch_v(16);

    for (int i = 0; i < 32; i++) {
        int buf = i & 1, oc = i * 16;
        __syncthreads();   // orders: prev out-reads vs Os writes; VPs(buf) store vs MMA reads
        if (i + 1 < 32) {
            store_v(buf ^ 1);
            if (i + 2 < 32) prefetch_v(oc + 32);
        }

        // residual x loads for THIS chunk (overlap with MMA)
        float4 pxv[4];
        #pragma unroll
        for (int r = 0; r < 4; r++) {
            int flat = r * 256 + tid;
            int pp = flat & 1;
            int t  = (flat >> 1) & 31;
            int o  = flat >> 6;
            pxv[r] = *reinterpret_cast<const float4*>(
                xg + ((size_t)(oc + o) * 32 + t) * 1024 + pp * 4);
        }

        float acc2[2][2][4];
        #pragma unroll
        for (int ii = 0; ii < 2; ii++)
            #pragma unroll
            for (int j = 0; j < 2; j++)
                #pragma unroll
                for (int r = 0; r < 4; r++) acc2[ii][j][r] = 0.f;

        const uint32_t* Vu = reinterpret_cast<const uint32_t*>(sm + 9472 + buf * 5376);
        #pragma unroll
        for (int kk = 0; kk < 32; kk += 8) {
            uint32_t a[2][4], bq[2][2];
            #pragma unroll
            for (int mf = 0; mf < 2; mf++) {
                int base = (mf * 16 + g) * GS_TSTR + (kk + tq) * 9 + px;
                a[mf][0] = Gu[base];
                a[mf][1] = Gu[base + 8 * GS_TSTR];
                a[mf][2] = Gu[base + 36];
                a[mf][3] = Gu[base + 8 * GS_TSTR + 36];
            }
            #pragma unroll
            for (int nf = 0; nf < 2; nf++) {
                int base = (kk + tq) * VP_SSTR + (nf * 8 + g) * 9 + px;
                bq[nf][0] = Vu[base];
                bq[nf][1] = Vu[base + 4 * VP_SSTR];
            }
            #pragma unroll
            for (int mf = 0; mf < 2; mf++)
                #pragma unroll
                for (int nf = 0; nf < 2; nf++)
                    MMA_TF32(acc2[mf][nf][0], acc2[mf][nf][1], acc2[mf][nf][2], acc2[mf][nf][3],
                             a[mf][0], a[mf][1], a[mf][2], a[mf][3],
                             bq[nf][0], bq[nf][1]);
        }

        #pragma unroll
        for (int mf = 0; mf < 2; mf++) {
            #pragma unroll
            for (int nf = 0; nf < 2; nf++) {
                int t = mf * 16 + g;
                int o = nf * 8 + tq * 2;
                Os[t * OS_TSTR + o * 10 + px]             = acc2[mf][nf][0];
                Os[t * OS_TSTR + (o + 1) * 10 + px]       = acc2[mf][nf][1];
                Os[(t + 8) * OS_TSTR + o * 10 + px]       = acc2[mf][nf][2];
                Os[(t + 8) * OS_TSTR + (o + 1) * 10 + px] = acc2[mf][nf][3];
            }
        }
        __syncthreads();

        #pragma unroll
        for (int r = 0; r < 4; r++) {
            int flat = r * 256 + tid;
            int pp = flat & 1;
            int t  = (flat >> 1) & 31;
            int o  = flat >> 6;
            size_t gg = pixbase + ((size_t)(oc + o) * 32 + t) * 1024 + pp * 4;
            int so = t * OS_TSTR + o * 10 + pp * 4;
            float4 ov;
            ov.x = Os[so]     + pxv[r].x;
            ov.y = Os[so + 1] + pxv[r].y;
            ov.z = Os[so + 2] + pxv[r].z;
            ov.w = Os[so + 3] + pxv[r].w;
            *reinterpret_cast<float4*>(out + gg) = ov;
        }
    }
}

// ---------------------------------------------------------------------------
extern "C" void kernel_launch(void* const* d_in, const int* in_sizes, int n_in,
                              void* d_out, int out_size)
{
    const float* x     = (const float*)d_in[0];
    const float* gamma = (const float*)d_in[1];
    const float* beta  = (const float*)d_in[2];
    const float* wq    = (const float*)d_in[3];
    const float* wk    = (const float*)d_in[4];
    const float* wv    = (const float*)d_in[5];
    const float* wproj = (const float*)d_in[6];
    float* out = (float*)d_out;

    cudaFuncSetAttribute(gemm_uv_f16, cudaFuncAttributeMaxDynamicSharedMemorySize,
                         GEMM_SMEM);
    cudaFuncSetAttribute(attn_mma, cudaFuncAttributeMaxDynamicSharedMemorySize,
                         ATTN_SMEM_FLOATS * 4);

    prep_w2<<<1024, 256>>>(wq, wk, wv, wproj, gamma, beta);
    conv_x16<<<dim3(512, 8, B_), 256>>>(x);
    reduce_stats<<<128, 128>>>();
    gemm_uv_f16<<<dim3(8, 256, B_), 128, GEMM_SMEM>>>();
    attn_mma<<<512, 256, ATTN_SMEM_FLOATS * 4>>>(x, gamma, beta, out);
}

// round 14
// speedup vs baseline: 1.1816x; 1.1816x over previous
#include <cuda_runtime.h>
#include <cuda_fp16.h>
#include <math.h>
#include <stdint.h>

#define B_   4
#define C_   512
#define T_   32
#define HW_  1024
#define NCOL (T_*HW_)            // 32768 columns per batch
#define TOT  (B_*C_*T_*HW_)

// Scratch
__device__ __half d_x16[TOT];      // fp16 x, [b][n][c] (n = t*1024+hw)
__device__ __half d_W16[1024*512]; // W2G = W2·diag(gamma), [m][k], fp16
__device__ __half d_u16[TOT];      // u  (fp16, [b][c][n])
__device__ __half d_vp16[TOT];     // v' (fp16, [b][c][n])
__device__ float  d_w2g1[1024];
__device__ float  d_w2b[1024];
__device__ float  d_psum[16384];
__device__ float  d_psum2[16384];
__device__ float  d_mean[B_*T_];
__device__ float  d_rstd[B_*T_];

__device__ __forceinline__ void cp16g(void* dst, const void* src) {
    unsigned d = (unsigned)__cvta_generic_to_shared(dst);
    asm volatile("cp.async.cg.shared.global [%0], [%1], 16;\n" :: "r"(d), "l"(src));
}

#define MMA_F16(d0,d1,d2,d3,a0,a1,a2,a3,b0,b1) \
    asm volatile("mma.sync.aligned.m16n8k16.row.col.f32.f16.f16.f32 " \
                 "{%0,%1,%2,%3},{%4,%5,%6,%7},{%8,%9},{%0,%1,%2,%3};" \
                 : "+f"(d0), "+f"(d1), "+f"(d2), "+f"(d3) \
                 : "r"(a0), "r"(a1), "r"(a2), "r"(a3), "r"(b0), "r"(b1))

#define MMA_TF32(d0,d1,d2,d3,a0,a1,a2,a3,b0,b1) \
    asm volatile("mma.sync.aligned.m16n8k8.row.col.f32.tf32.tf32.f32 " \
                 "{%0,%1,%2,%3},{%4,%5,%6,%7},{%8,%9},{%0,%1,%2,%3};" \
                 : "+f"(d0), "+f"(d1), "+f"(d2), "+f"(d3) \
                 : "r"(a0), "r"(a1), "r"(a2), "r"(a3), "r"(b0), "r"(b1))

#define LDSM_X4(r0,r1,r2,r3,addr) \
    asm volatile("ldmatrix.sync.aligned.m8n8.x4.shared.b16 {%0,%1,%2,%3}, [%4];" \
                 : "=r"(r0), "=r"(r1), "=r"(r2), "=r"(r3) : "r"(addr))

__device__ __forceinline__ float tf32r(float x) {
    uint32_t r;
    asm("cvt.rna.tf32.f32 %0, %1;" : "=r"(r) : "f"(x));
    return __uint_as_float(r);
}

// ---------------------------------------------------------------------------
// prep_w2 (R10 verbatim)
// ---------------------------------------------------------------------------
__global__ void prep_w2(const float* __restrict__ wq, const float* __restrict__ wk,
                        const float* __restrict__ wv, const float* __restrict__ wproj,
                        const float* __restrict__ gamma, const float* __restrict__ beta)
{
    int m = blockIdx.x;
    int tid = threadIdx.x;
    float lg = 0.f, lb = 0.f;
    #pragma unroll
    for (int jj = 0; jj < 2; jj++) {
        int j = jj * 256 + tid;
        float acc = 0.f;
        if (m < 512) {
            #pragma unroll 4
            for (int o = 0; o < 512; o++)
                acc += wq[o*512 + m] * wk[o*512 + j];
        } else {
            int i = m - 512;
            #pragma unroll 4
            for (int c = 0; c < 512; c++)
                acc += wproj[i*512 + c] * wv[c*512 + j];
        }
        __half wh = __float2half(acc * gamma[j]);
        d_W16[(size_t)m * 512 + j] = wh;
        lg += __half2float(wh);
        lb += acc * beta[j];
    }
    __shared__ float red[16];
    #pragma unroll
    for (int o = 16; o > 0; o >>= 1) {
        lg += __shfl_down_sync(0xffffffffu, lg, o);
        lb += __shfl_down_sync(0xffffffffu, lb, o);
    }
    int w = tid >> 5;
    if ((tid & 31) == 0) { red[w] = lg; red[8 + w] = lb; }
    __syncthreads();
    if (tid == 0) {
        float G = 0.f, Bv = 0.f;
        for (int k = 0; k < 8; k++) { G += red[k]; Bv += red[8 + k]; }
        d_w2g1[m] = G;
        d_w2b[m]  = Bv;
    }
}

// ---------------------------------------------------------------------------
// conv_x16 + LN partial sums (R10 verbatim)
// ---------------------------------------------------------------------------
__global__ void conv_x16(const float* __restrict__ x)
{
    __shared__ float sT[64][65];
    __shared__ float rsum[8], rsum2[8];
    int b   = blockIdx.z;
    int c0  = blockIdx.y * 64;
    int n0t = blockIdx.x * 64;
    int tid = threadIdx.x;
    const float* xb = x + (size_t)b * C_ * NCOL;
    float s = 0.f, ss = 0.f;
    #pragma unroll
    for (int r = 0; r < 4; r++) {
        int flat = r * 256 + tid;
        int cr = flat >> 4, nq = flat & 15;
        float4 v = *reinterpret_cast<const float4*>(
            xb + (size_t)(c0 + cr) * NCOL + n0t + nq * 4);
        sT[cr][nq*4+0] = v.x; sT[cr][nq*4+1] = v.y;
        sT[cr][nq*4+2] = v.z; sT[cr][nq*4+3] = v.w;
        s  += v.x + v.y + v.z + v.w;
        ss += v.x*v.x + v.y*v.y + v.z*v.z + v.w*v.w;
    }
    #pragma unroll
    for (int o = 16; o > 0; o >>= 1) {
        s  += __shfl_down_sync(0xffffffffu, s,  o);
        ss += __shfl_down_sync(0xffffffffu, ss, o);
    }
    if ((tid & 31) == 0) { rsum[tid >> 5] = s; rsum2[tid >> 5] = ss; }
    __syncthreads();
    if (tid == 0) {
        float S = 0.f, SS = 0.f;
        #pragma unroll
        for (int k = 0; k < 8; k++) { S += rsum[k]; SS += rsum2[k]; }
        int t = blockIdx.x >> 4, nIn = blockIdx.x & 15;
        int pid = ((b * 32 + t) * 8 + blockIdx.y) * 16 + nIn;
        d_psum[pid]  = S;
        d_psum2[pid] = SS;
    }
    int nr = tid >> 2, cq = tid & 3;
    uint32_t pk[8];
    #pragma unroll
    for (int j = 0; j < 8; j++) {
        __half2 h2 = __floats2half2_rn(sT[cq*16 + j*2][nr], sT[cq*16 + j*2 + 1][nr]);
        pk[j] = *reinterpret_cast<uint32_t*>(&h2);
    }
    __half* dst = d_x16 + ((size_t)b * NCOL + n0t + nr) * 512 + c0 + cq * 16;
    *reinterpret_cast<uint4*>(dst)     = make_uint4(pk[0], pk[1], pk[2], pk[3]);
    *reinterpret_cast<uint4*>(dst + 8) = make_uint4(pk[4], pk[5], pk[6], pk[7]);
}

__global__ void reduce_stats()
{
    int g = blockIdx.x;
    int tid = threadIdx.x;
    float s  = d_psum[g * 128 + tid];
    float ss = d_psum2[g * 128 + tid];
    #pragma unroll
    for (int o = 16; o > 0; o >>= 1) {
        s  += __shfl_down_sync(0xffffffffu, s,  o);
        ss += __shfl_down_sync(0xffffffffu, ss, o);
    }
    __shared__ float sm[8];
    if ((tid & 31) == 0) { sm[tid >> 5] = s; sm[4 + (tid >> 5)] = ss; }
    __syncthreads();
    if (tid == 0) {
        float S = sm[0] + sm[1] + sm[2] + sm[3];
        float SS = sm[4] + sm[5] + sm[6] + sm[7];
        float invn = 1.f / (float)(C_ * HW_);
        float m = S * invn;
        float var = SS * invn - m * m;
        d_mean[g] = m;
        d_rstd[g] = rsqrtf(var + 1e-6f);
    }
}

// ---------------------------------------------------------------------------
// fp16 GEMM (R10 structure, ldmatrix fragment loads)
// ---------------------------------------------------------------------------
#define AROW 40                  // halfs per k-row (80 bytes)
#define STH  (128*AROW)
#define STAGEH (2*STH)
#define GEMM_SMEM (4*STAGEH*2)   // 81920 B

__global__ __launch_bounds__(128, 2) void gemm_uv_f16()
{
    extern __shared__ __half smh[];
    int b  = blockIdx.z;
    int m0 = blockIdx.x * 128;
    int n0 = blockIdx.y * 128;
    const __half* xb = d_x16 + (size_t)b * NCOL * 512;
    int tid  = threadIdx.x;
    int lane = tid & 31;
    int w    = tid >> 5;
    int warpM = w >> 1, warpN = w & 1;
    int g = lane >> 2, tq = lane & 3;

    // ldmatrix per-lane address offsets (bytes within a tile)
    uint32_t smbase = (uint32_t)__cvta_generic_to_shared(smh);
    uint32_t aposA = (uint32_t)((lane & 15) * 80 + (lane >> 4) * 16);
    uint32_t aposB = (uint32_t)((((lane & 7) + ((lane >> 4) << 3)) * 80)
                                + (((lane >> 3) & 1) * 16));

    float acc[4][8][4];
    #pragma unroll
    for (int i = 0; i < 4; i++)
        #pragma unroll
        for (int j = 0; j < 8; j++)
            #pragma unroll
            for (int r = 0; r < 4; r++) acc[i][j][r] = 0.f;

    auto load_stage = [&](int k0, int buf) {
        __half* As = smh + buf * STAGEH;
        __half* Bs = As + STH;
        #pragma unroll
        for (int r = 0; r < 4; r++) {
            int ch = r * 128 + tid;
            int row = ch >> 2;
            int q   = ch & 3;
            cp16g(As + row * AROW + q * 8, &d_W16[(size_t)(m0 + row) * 512 + k0 + q * 8]);
            cp16g(Bs + row * AROW + q * 8, &xb[(size_t)(n0 + row) * 512 + k0 + q * 8]);
        }
    };

    #pragma unroll
    for (int p = 0; p < 3; p++) {
        load_stage(p * 32, p);
        asm volatile("cp.async.commit_group;\n");
    }

    for (int it = 0; it < 16; it++) {
        asm volatile("cp.async.wait_group 2;\n");
        __syncthreads();

        uint32_t aBase = smbase + (uint32_t)((it & 3) * STAGEH * 2)
                       + (uint32_t)(warpM * 64 * 80) + aposA;
        uint32_t bBase = smbase + (uint32_t)((it & 3) * STAGEH * 2 + STH * 2)
                       + (uint32_t)(warpN * 64 * 80) + aposB;

        #pragma unroll
        for (int kc = 0; kc < 2; kc++) {        // two k16 chunks (byte offset 0 / 32)
            uint32_t a[4][4], bq[8][2];
            #pragma unroll
            for (int mf = 0; mf < 4; mf++)
                LDSM_X4(a[mf][0], a[mf][1], a[mf][2], a[mf][3],
                        aBase + (uint32_t)(mf * 16 * 80 + kc * 32));
            #pragma unroll
            for (int pr = 0; pr < 4; pr++)       // nf pairs: (2pr, 2pr+1)
                LDSM_X4(bq[2*pr][0], bq[2*pr][1], bq[2*pr+1][0], bq[2*pr+1][1],
                        bBase + (uint32_t)(pr * 16 * 80 + kc * 32));
            #pragma unroll
            for (int mf = 0; mf < 4; mf++)
                #pragma unroll
                for (int nf = 0; nf < 8; nf++)
                    MMA_F16(acc[mf][nf][0], acc[mf][nf][1], acc[mf][nf][2], acc[mf][nf][3],
                            a[mf][0], a[mf][1], a[mf][2], a[mf][3],
                            bq[nf][0], bq[nf][1]);
        }
        if (it + 3 < 16)
            load_stage((it + 3) * 32, (it + 3) & 3);
        asm volatile("cp.async.commit_group;\n");
    }

    int tcol = blockIdx.y >> 3;
    int gidx = b * 32 + tcol;
    float rstdv = d_rstd[gidx];
    float rm    = rstdv * d_mean[gidx];
    bool isU = (m0 < 512);
    __half* outb = isU ? (d_u16  + (size_t)(b * 512 + m0)       * NCOL)
                       : (d_vp16 + (size_t)(b * 512 + m0 - 512) * NCOL);
    #pragma unroll
    for (int mf = 0; mf < 4; mf++) {
        int mrow = warpM * 64 + mf * 16 + g;
        int mg0 = m0 + mrow, mg1 = m0 + mrow + 8;
        float bias0 = d_w2b[mg0] - rm * d_w2g1[mg0];
        float bias1 = d_w2b[mg1] - rm * d_w2g1[mg1];
        #pragma unroll
        for (int nf = 0; nf < 8; nf++) {
            int ncol = n0 + warpN * 64 + nf * 8 + tq * 2;
            __half2 lo = __floats2half2_rn(rstdv * acc[mf][nf][0] + bias0,
                                           rstdv * acc[mf][nf][1] + bias0);
            __half2 hi = __floats2half2_rn(rstdv * acc[mf][nf][2] + bias1,
                                           rstdv * acc[mf][nf][3] + bias1);
            *reinterpret_cast<__half2*>(outb + (size_t)mrow * NCOL + ncol)       = lo;
            *reinterpret_cast<__half2*>(outb + (size_t)(mrow + 8) * NCOL + ncol) = hi;
        }
    }
}

// ---------------------------------------------------------------------------
// attn (R10 verbatim — proven local optimum; 128-reg/80KB envelope)
// ---------------------------------------------------------------------------
#define HS_CSTR 296
#define GS_TSTR 292
#define VP_SSTR 168
#define OS_TSTR 164
#define ATTN_SMEM_FLOATS (9344 + 5376 + 5248)   // 19968 floats

__global__ __launch_bounds__(256, 2) void attn_mma(const float* __restrict__ x,
                                                   const float* __restrict__ gamma,
                                                   const float* __restrict__ beta,
                                                   float* __restrict__ out)
{
    extern __shared__ float sm[];
    float* Hs  = sm;
    float* Us  = sm + 4736;
    float* Gs  = sm;
    float* VPs = sm + 9344;
    float* Os  = sm + 14720;
    float* gus = sm + 14720;
    float* bus = sm + 14976;
    float* smG = sm + 15800;
    float* smB = sm + 15816;

    int blk = blockIdx.x;
    int b   = blk >> 7;
    int hw0 = (blk & 127) * 8;
    int tid  = threadIdx.x;
    int lane = tid & 31;
    int px   = tid >> 5;
    int g = lane >> 2, tq = lane & 3;
    const size_t pixbase = (size_t)b * C_ * T_ * HW_ + hw0;
    const float*  xg = x      + pixbase;
    const __half* xh = d_x16  + (size_t)b * NCOL * 512;
    const __half* ug = d_u16  + pixbase;
    const __half* vg = d_vp16 + pixbase;

    int s_ = tid >> 3, px_ = tid & 7;
    float gu = 0.f, bu = 0.f;

    float acc1[2][4][4];
    #pragma unroll
    for (int i = 0; i < 2; i++)
        #pragma unroll
        for (int j = 0; j < 4; j++)
            #pragma unroll
            for (int r = 0; r < 4; r++) acc1[i][j][r] = 0.f;

    uint4 pxh[2], pu4[2];
    auto prefetch1 = [&](int c0) {
        #pragma unroll
        for (int r = 0; r < 2; r++) {
            int flat = r * 256 + tid;
            int q   = flat & 1;
            int pxl = (flat >> 1) & 7;
            int t   = flat >> 4;
            pxh[r] = *reinterpret_cast<const uint4*>(
                xh + ((size_t)t * 1024 + hw0 + pxl) * 512 + c0 + q * 8);
        }
        #pragma unroll
        for (int r = 0; r < 2; r++) {
            int flat = r * 256 + tid;
            int c = flat >> 5, t = flat & 31;
            pu4[r] = *reinterpret_cast<const uint4*>(
                ug + ((size_t)(c0 + c) * 32 + t) * 1024);
        }
    };
    auto store1 = [&](int c0) {
        #pragma unroll
        for (int r = 0; r < 2; r++) {
            int flat = r * 256 + tid;
            int q   = flat & 1;
            int pxl = (flat >> 1) & 7;
            int t   = flat >> 4;
            const __half2* hp = reinterpret_cast<const __half2*>(&pxh[r]);
            #pragma unroll
            for (int j = 0; j < 4; j++) {
                float2 f = __half22float2(hp[j]);
                int c = q * 8 + j * 2;
                Hs[(c)     * HS_CSTR + t * 9 + pxl] = gamma[c0 + c]     * f.x;
                Hs[(c + 1) * HS_CSTR + t * 9 + pxl] = gamma[c0 + c + 1] * f.y;
            }
        }
        #pragma unroll
        for (int r = 0; r < 2; r++) {
            int flat = r * 256 + tid;
            int c = flat >> 5, t = flat & 31;
            int so = c * HS_CSTR + t * 9;
            const __half2* hp = reinterpret_cast<const __half2*>(&pu4[r]);
            #pragma unroll
            for (int j = 0; j < 4; j++) {
                float2 f = __half22float2(hp[j]);
                Us[so + j*2]     = f.x;
                Us[so + j*2 + 1] = f.y;
            }
        }
    };

    prefetch1(0);
    for (int c0 = 0; c0 < 512; c0 += 16) {
        store1(c0);
        if (tid < 16)       smG[tid]      = gamma[c0 + tid];
        else if (tid < 32)  smB[tid - 16] = beta[c0 + tid - 16];
        __syncthreads();
        if (c0 + 16 < 512) prefetch1(c0 + 16);

        const uint32_t* Hu = reinterpret_cast<const uint32_t*>(Hs);
        const uint32_t* Uu = reinterpret_cast<const uint32_t*>(Us);
        #pragma unroll
        for (int kk = 0; kk < 16; kk += 8) {
            uint32_t a[2][4], bq[4][2];
            #pragma unroll
            for (int mf = 0; mf < 2; mf++) {
                int base = (kk + tq) * HS_CSTR + (mf * 16 + g) * 9 + px;
                a[mf][0] = Hu[base];
                a[mf][1] = Hu[base + 72];
                a[mf][2] = Hu[base + 4 * HS_CSTR];
                a[mf][3] = Hu[base + 4 * HS_CSTR + 72];
            }
            #pragma unroll
            for (int nf = 0; nf < 4; nf++) {
                int base = (kk + tq) * HS_CSTR + (nf * 8 + g) * 9 + px;
                bq[nf][0] = Uu[base];
                bq[nf][1] = Uu[base + 4 * HS_CSTR];
            }
            #pragma unroll
            for (int mf = 0; mf < 2; mf++)
                #pragma unroll
                for (int nf = 0; nf < 4; nf++)
                    MMA_TF32(acc1[mf][nf][0], acc1[mf][nf][1], acc1[mf][nf][2], acc1[mf][nf][3],
                             a[mf][0], a[mf][1], a[mf][2], a[mf][3],
                             bq[nf][0], bq[nf][1]);
        }
        #pragma unroll
        for (int c = 0; c < 16; c++) {
            float uv = Us[c * HS_CSTR + s_ * 9 + px_];
            gu += smG[c] * uv;
            bu += smB[c] * uv;
        }
        __syncthreads();
    }

    gus[s_ * 8 + px_] = gu;
    bus[s_ * 8 + px_] = bu;
    __syncthreads();

    const float scale = 0.044194173824159216f;
    #pragma unroll
    for (int mf = 0; mf < 2; mf++) {
        int t0 = mf * 16 + g, t1 = t0 + 8;
        float r0 = d_rstd[b*32 + t0], m0v = d_mean[b*32 + t0];
        float r1 = d_rstd[b*32 + t1], m1v = d_mean[b*32 + t1];
        #pragma unroll
        for (int nf = 0; nf < 4; nf++) {
            int s0 = nf * 8 + tq * 2, s1 = s0 + 1;
            float gu0 = gus[s0*8 + px], bu0 = bus[s0*8 + px];
            float gu1 = gus[s1*8 + px], bu1 = bus[s1*8 + px];
            Gs[t0 * GS_TSTR + s0 * 9 + px] = (r0*(acc1[mf][nf][0] - m0v*gu0) + bu0) * scale;
            Gs[t0 * GS_TSTR + s1 * 9 + px] = (r0*(acc1[mf][nf][1] - m0v*gu1) + bu1) * scale;
            Gs[t1 * GS_TSTR + s0 * 9 + px] = (r1*(acc1[mf][nf][2] - m1v*gu0) + bu0) * scale;
            Gs[t1 * GS_TSTR + s1 * 9 + px] = (r1*(acc1[mf][nf][3] - m1v*gu1) + bu1) * scale;
        }
    }
    __syncthreads();

    {
        int pxs = tid & 7;
        int t   = tid >> 3;
        int gb  = t * GS_TSTR + pxs;
        float mx = -1e30f;
        for (int s = 0; s <= t; s++) mx = fmaxf(mx, Gs[gb + s * 9]);
        float Z = 0.f;
        for (int s = 0; s <= t; s++) Z += __expf(Gs[gb + s * 9] - mx);
        float iz = 1.f / Z;
        for (int s = 0; s < 32; s++) {
            float v = (s <= t) ? __expf(Gs[gb + s * 9] - mx) * iz : 0.f;
            Gs[gb + s * 9] = tf32r(v);
        }
    }
    __syncthreads();

    const uint32_t* Gu = reinterpret_cast<const uint32_t*>(Gs);
    uint4 pv4[2];
    auto prefetch_v = [&](int oc) {
        #pragma unroll
        for (int r = 0; r < 2; r++) {
            int flat = r * 256 + tid;
            int s = flat >> 4, o = flat & 15;
            pv4[r] = *reinterpret_cast<const uint4*>(
                vg + ((size_t)(oc + o) * 32 + s) * 1024);
        }
    };

    prefetch_v(0);
    for (int oc = 0; oc < 512; oc += 16) {
        #pragma unroll
        for (int r = 0; r < 2; r++) {
            int flat = r * 256 + tid;
            int s = flat >> 4, o = flat & 15;
            int so = s * VP_SSTR + o * 9;
            const __half2* hp = reinterpret_cast<const __half2*>(&pv4[r]);
            #pragma unroll
            for (int j = 0; j < 4; j++) {
                float2 f = __half22float2(hp[j]);
                VPs[so + j*2]     = f.x;
                VPs[so + j*2 + 1] = f.y;
            }
        }
        __syncthreads();
        if (oc + 16 < 512) prefetch_v(oc + 16);

        float4 pxv[4];
        #pragma unroll
        for (int r = 0; r < 4; r++) {
            int flat = r * 256 + tid;
            int pp = flat & 1;
            int t  = (flat >> 1) & 31;
            int o  = flat >> 6;
            pxv[r] = *reinterpret_cast<const float4*>(
                xg + ((size_t)(oc + o) * 32 + t) * 1024 + pp * 4);
        }

        float acc2[2][2][4];
        #pragma unroll
        for (int ii = 0; ii < 2; ii++)
            #pragma unroll
            for (int j = 0; j < 2; j++)
                #pragma unroll
                for (int r = 0; r < 4; r++) acc2[ii][j][r] = 0.f;

        const uint32_t* Vu = reinterpret_cast<const uint32_t*>(VPs);
        #pragma unroll
        for (int kk = 0; kk < 32; kk += 8) {
            uint32_t a[2][4], bq[2][2];
            #pragma unroll
            for (int mf = 0; mf < 2; mf++) {
                int base = (mf * 16 + g) * GS_TSTR + (kk + tq) * 9 + px;
                a[mf][0] = Gu[base];
                a[mf][1] = Gu[base + 8 * GS_TSTR];
                a[mf][2] = Gu[base + 36];
                a[mf][3] = Gu[base + 8 * GS_TSTR + 36];
            }
            #pragma unroll
            for (int nf = 0; nf < 2; nf++) {
                int base = (kk + tq) * VP_SSTR + (nf * 8 + g) * 9 + px;
                bq[nf][0] = Vu[base];
                bq[nf][1] = Vu[base + 4 * VP_SSTR];
            }
            #pragma unroll
            for (int mf = 0; mf < 2; mf++)
                #pragma unroll
                for (int nf = 0; nf < 2; nf++)
                    MMA_TF32(acc2[mf][nf][0], acc2[mf][nf][1], acc2[mf][nf][2], acc2[mf][nf][3],
                             a[mf][0], a[mf][1], a[mf][2], a[mf][3],
                             bq[nf][0], bq[nf][1]);
        }

        #pragma unroll
        for (int mf = 0; mf < 2; mf++) {
            #pragma unroll
            for (int nf = 0; nf < 2; nf++) {
                int t = mf * 16 + g;
                int o = nf * 8 + tq * 2;
                Os[t * OS_TSTR + o * 10 + px]             = acc2[mf][nf][0];
                Os[t * OS_TSTR + (o + 1) * 10 + px]       = acc2[mf][nf][1];
                Os[(t + 8) * OS_TSTR + o * 10 + px]       = acc2[mf][nf][2];
                Os[(t + 8) * OS_TSTR + (o + 1) * 10 + px] = acc2[mf][nf][3];
            }
        }
        __syncthreads();

        #pragma unroll
        for (int r = 0; r < 4; r++) {
            int flat = r * 256 + tid;
            int pp = flat & 1;
            int t  = (flat >> 1) & 31;
            int o  = flat >> 6;
            size_t gg = pixbase + ((size_t)(oc + o) * 32 + t) * 1024 + pp * 4;
            int so = t * OS_TSTR + o * 10 + pp * 4;
            float4 ov;
            ov.x = Os[so]     + pxv[r].x;
            ov.y = Os[so + 1] + pxv[r].y;
            ov.z = Os[so + 2] + pxv[r].z;
            ov.w = Os[so + 3] + pxv[r].w;
            *reinterpret_cast<float4*>(out + gg) = ov;
        }
        __syncthreads();
    }
}

// ---------------------------------------------------------------------------
extern "C" void kernel_launch(void* const* d_in, const int* in_sizes, int n_in,
                              void* d_out, int out_size)
{
    const float* x     = (const float*)d_in[0];
    const float* gamma = (const float*)d_in[1];
    const float* beta  = (const float*)d_in[2];
    const float* wq    = (const float*)d_in[3];
    const float* wk    = (const float*)d_in[4];
    const float* wv    = (const float*)d_in[5];
    const float* wproj = (const float*)d_in[6];
    float* out = (float*)d_out;

    cudaFuncSetAttribute(gemm_uv_f16, cudaFuncAttributeMaxDynamicSharedMemorySize,
                         GEMM_SMEM);
    cudaFuncSetAttribute(attn_mma, cudaFuncAttributeMaxDynamicSharedMemorySize,
                         ATTN_SMEM_FLOATS * 4);

    prep_w2<<<1024, 256>>>(wq, wk, wv, wproj, gamma, beta);
    conv_x16<<<dim3(512, 8, B_), 256>>>(x);
    reduce_stats<<<128, 128>>>();
    gemm_uv_f16<<<dim3(8, 256, B_), 128, GEMM_SMEM>>>();
    attn_mma<<<512, 256, ATTN_SMEM_FLOATS * 4>>>(x, gamma, beta, out);
}